// round 2
// baseline (speedup 1.0000x reference)
#include <cuda_runtime.h>
#include <cstdint>

// ----------------------------------------------------------------------------
// Dims
// ----------------------------------------------------------------------------
#define S_TOK 8192
#define D_IN  4096
#define NHEAD 8
#define NGRP  4
#define HDIM  128
#define NQ    4096
#define NK    1024
#define NF    5120

// GEMM tiling (legacy mma.sync tf32 path — base sm_100 compatible)
#define BM 128
#define BN 256
#define BK 32
#define STAGES 4
#define KT (D_IN / BK)          // 128
#define PITCH (BK + 4)          // 36 floats, conflict-free frag LDS
#define A_STG_FLOATS (BM * PITCH)   // 4608
#define B_STG_FLOATS (BN * PITCH)   // 9216
#define SMEM_FLOATS (STAGES * (A_STG_FLOATS + B_STG_FLOATS))
#define SMEM_BYTES  (SMEM_FLOATS * 4)   // 221184

// Scratch: C[s, f]  (f<4096 -> Q features, f>=4096 -> K features)
__device__ float g_C[(size_t)S_TOK * NF];

// ----------------------------------------------------------------------------
// helpers
// ----------------------------------------------------------------------------
__device__ __forceinline__ uint32_t smem_u32(const void* p) {
    uint32_t a;
    asm("{ .reg .u64 t; cvta.to.shared.u64 t, %1; cvt.u32.u64 %0, t; }"
        : "=r"(a) : "l"(p));
    return a;
}

__device__ __forceinline__ void cp_async16(uint32_t dst, const void* src) {
    asm volatile("cp.async.cg.shared.global [%0], [%1], 16;"
                 :: "r"(dst), "l"(src) : "memory");
}
__device__ __forceinline__ void cp_commit() {
    asm volatile("cp.async.commit_group;" ::: "memory");
}
template <int N>
__device__ __forceinline__ void cp_wait() {
    asm volatile("cp.async.wait_group %0;" :: "n"(N) : "memory");
}

__device__ __forceinline__ uint32_t to_tf32(float f) {
    uint32_t r;
    asm("cvt.rna.tf32.f32 %0, %1;" : "=r"(r) : "f"(f));
    return r;
}

__device__ __forceinline__ void mma_tf32(float* c, const uint32_t* a,
                                         const uint32_t* b) {
    asm volatile(
        "mma.sync.aligned.m16n8k8.row.col.f32.tf32.tf32.f32 "
        "{%0,%1,%2,%3}, {%4,%5,%6,%7}, {%8,%9}, {%0,%1,%2,%3};"
        : "+f"(c[0]), "+f"(c[1]), "+f"(c[2]), "+f"(c[3])
        : "r"(a[0]), "r"(a[1]), "r"(a[2]), "r"(a[3]), "r"(b[0]), "r"(b[1]));
}

// ----------------------------------------------------------------------------
// Kernel 1: fused projection GEMM  C[8192, 5120] = hs * [q_w ; k_w]^T
// grid: (NF/BN = 20, S_TOK/BM = 64), 512 threads (16 warps, 4x4 warp grid)
// ----------------------------------------------------------------------------
__global__ void __launch_bounds__(512, 1)
gemm_kernel(const float* __restrict__ A,
            const float* __restrict__ Wq,
            const float* __restrict__ Wk)
{
    extern __shared__ float sm[];
    float* As = sm;                                   // [STAGES][BM][PITCH]
    float* Bs = sm + STAGES * A_STG_FLOATS;           // [STAGES][BN][PITCH]

    const int tid   = threadIdx.x;
    const int ntile = blockIdx.x;   // 0..19
    const int mtile = blockIdx.y;   // 0..63

    const float* Asrc = A + (size_t)mtile * BM * D_IN;
    const float* Bsrc = (ntile < 16)
        ? Wq + (size_t)ntile * BN * D_IN
        : Wk + (size_t)(ntile - 16) * BN * D_IN;

    const uint32_t as_base = smem_u32(As);
    const uint32_t bs_base = smem_u32(Bs);

    // per-thread load coords (16B granules)
    const int a_row0 = tid >> 3;          // +64 for second granule
    const int cols4  = (tid & 7) * 4;     // float col of granule

    // stage loader: A = 1024 granules (2/thread), B = 2048 granules (4/thread)
    auto load_stage = [&](int kt, int s) {
        const uint32_t a_st = as_base + (uint32_t)s * A_STG_FLOATS * 4;
        const uint32_t b_st = bs_base + (uint32_t)s * B_STG_FLOATS * 4;
        const int kc = kt * BK + cols4;
        #pragma unroll
        for (int i = 0; i < 2; i++) {
            const int row = a_row0 + i * 64;
            cp_async16(a_st + (row * PITCH + cols4) * 4,
                       Asrc + (size_t)row * D_IN + kc);
        }
        #pragma unroll
        for (int i = 0; i < 4; i++) {
            const int row = a_row0 + i * 64;
            cp_async16(b_st + (row * PITCH + cols4) * 4,
                       Bsrc + (size_t)row * D_IN + kc);
        }
        cp_commit();
    };

    load_stage(0, 0);
    load_stage(1, 1);
    load_stage(2, 2);

    const int wid = tid >> 5;
    const int ln  = tid & 31;
    const int wm  = wid & 3;    // 0..3 -> 32-row strip
    const int wn  = wid >> 2;   // 0..3 -> 64-col strip

    float acc[2][8][4];
    #pragma unroll
    for (int mi = 0; mi < 2; mi++)
        #pragma unroll
        for (int ni = 0; ni < 8; ni++)
            #pragma unroll
            for (int j = 0; j < 4; j++) acc[mi][ni][j] = 0.0f;

    const int lr = ln >> 2;     // 0..7
    const int lc = ln & 3;      // 0..3

    for (int kt = 0; kt < KT; kt++) {
        const int s = kt & (STAGES - 1);
        cp_wait<2>();
        __syncthreads();
        if (kt + 3 < KT) load_stage(kt + 3, (kt + 3) & (STAGES - 1));

        const float* Ast = As + s * A_STG_FLOATS;
        const float* Bst = Bs + s * B_STG_FLOATS;

        #pragma unroll
        for (int ks = 0; ks < 4; ks++) {
            const int k0 = ks * 8;
            uint32_t af[2][4], bf[8][2];
            #pragma unroll
            for (int mi = 0; mi < 2; mi++) {
                const int r0 = wm * 32 + mi * 16;
                const float* p = Ast + (r0 + lr) * PITCH + k0 + lc;
                af[mi][0] = to_tf32(p[0]);
                af[mi][1] = to_tf32(p[8 * PITCH]);
                af[mi][2] = to_tf32(p[4]);
                af[mi][3] = to_tf32(p[8 * PITCH + 4]);
            }
            #pragma unroll
            for (int ni = 0; ni < 8; ni++) {
                const int n0 = wn * 64 + ni * 8;
                const float* p = Bst + (n0 + lr) * PITCH + k0 + lc;
                bf[ni][0] = to_tf32(p[0]);
                bf[ni][1] = to_tf32(p[4]);
            }
            #pragma unroll
            for (int mi = 0; mi < 2; mi++)
                #pragma unroll
                for (int ni = 0; ni < 8; ni++)
                    mma_tf32(acc[mi][ni], af[mi], bf[ni]);
        }
    }

    // epilogue: write 128x256 tile to g_C
    const size_t fbase = (ntile < 16) ? (size_t)ntile * BN
                                      : (size_t)NQ + (size_t)(ntile - 16) * BN;
    #pragma unroll
    for (int mi = 0; mi < 2; mi++) {
        const int row = mtile * BM + wm * 32 + mi * 16 + lr;
        float* dst = g_C + (size_t)row * NF + fbase + wn * 64 + 2 * lc;
        #pragma unroll
        for (int ni = 0; ni < 8; ni++) {
            *reinterpret_cast<float2*>(dst + ni * 8) =
                make_float2(acc[mi][ni][0], acc[mi][ni][1]);
            *reinterpret_cast<float2*>(dst + ni * 8 + 8 * NF) =
                make_float2(acc[mi][ni][2], acc[mi][ni][3]);
        }
    }
}

// ----------------------------------------------------------------------------
// Kernel 2: per-token score epilogue (warp h of block s handles head h)
// ----------------------------------------------------------------------------
__global__ void __launch_bounds__(256)
score_kernel(const float* __restrict__ q_b, const float* __restrict__ q_nw,
             const float* __restrict__ k_nw, const float* __restrict__ k_base,
             const float* __restrict__ bias, float* __restrict__ out)
{
    const int s = blockIdx.x;
    const int h = threadIdx.x >> 5;
    const int lane = threadIdx.x & 31;
    const float* Crow = g_C + (size_t)s * NF;

    // k head RMS norm
    float4 kv = *reinterpret_cast<const float4*>(Crow + NQ + h * HDIM + lane * 4);
    float ss = kv.x * kv.x + kv.y * kv.y + kv.z * kv.z + kv.w * kv.w;
    #pragma unroll
    for (int o = 16; o > 0; o >>= 1) ss += __shfl_xor_sync(0xffffffffu, ss, o);
    const float rk = rsqrtf(ss * (1.0f / HDIM) + 1e-6f);
    float4 knw = *reinterpret_cast<const float4*>(k_nw + lane * 4);
    const float kn0 = kv.x * rk * knw.x, kn1 = kv.y * rk * knw.y;
    const float kn2 = kv.z * rk * knw.z, kn3 = kv.w * rk * knw.w;

    float4 kb  = *reinterpret_cast<const float4*>(k_base + h * HDIM + lane * 4);
    float4 qnw = *reinterpret_cast<const float4*>(q_nw + lane * 4);

    const float inv_scale = 0.08838834764831845f;   // 1/sqrt(128)
    float acc = 0.0f;

    #pragma unroll
    for (int g = 0; g < NGRP; g++) {
        const int f0 = h * (NGRP * HDIM) + g * HDIM + lane * 4;
        float4 qv  = *reinterpret_cast<const float4*>(Crow + f0);
        float4 qbv = *reinterpret_cast<const float4*>(q_b + f0);
        const float q0 = qv.x + qbv.x, q1 = qv.y + qbv.y;
        const float q2 = qv.z + qbv.z, q3 = qv.w + qbv.w;

        float qs = q0 * q0 + q1 * q1 + q2 * q2 + q3 * q3;
        #pragma unroll
        for (int o = 16; o > 0; o >>= 1) qs += __shfl_xor_sync(0xffffffffu, qs, o);
        const float rq = rsqrtf(qs * (1.0f / HDIM) + 1e-6f);

        const float qn0 = q0 * rq * qnw.x, qn1 = q1 * rq * qnw.y;
        const float qn2 = q2 * rq * qnw.z, qn3 = q3 * rq * qnw.w;

        float dm = kn0 * qn0 + kn1 * qn1 + kn2 * qn2 + kn3 * qn3;
        float db = kb.x * qn0 + kb.y * qn1 + kb.z * qn2 + kb.w * qn3;
        #pragma unroll
        for (int o = 16; o > 0; o >>= 1) {
            dm += __shfl_xor_sync(0xffffffffu, dm, o);
            db += __shfl_xor_sync(0xffffffffu, db, o);
        }

        const float logit = dm * inv_scale + bias[h * NGRP + g];
        acc += 1.0f / (1.0f + expf(db * inv_scale - logit));
    }

    if (lane == 0) out[(size_t)h * S_TOK + s] = acc * 0.25f;
}

// ----------------------------------------------------------------------------
// Host launch
// ----------------------------------------------------------------------------
extern "C" void kernel_launch(void* const* d_in, const int* in_sizes, int n_in,
                              void* d_out, int out_size) {
    (void)in_sizes; (void)n_in; (void)out_size;

    static bool attr_done = false;
    if (!attr_done) {
        cudaFuncSetAttribute(gemm_kernel,
                             cudaFuncAttributeMaxDynamicSharedMemorySize,
                             SMEM_BYTES);
        attr_done = true;
    }

    gemm_kernel<<<dim3(NF / BN, S_TOK / BM), 512, SMEM_BYTES>>>(
        (const float*)d_in[0],   // hidden_states
        (const float*)d_in[1],   // q_w
        (const float*)d_in[3]);  // k_w

    score_kernel<<<S_TOK, 256>>>(
        (const float*)d_in[2],   // q_b
        (const float*)d_in[4],   // q_norm_w
        (const float*)d_in[5],   // k_norm_w
        (const float*)d_in[6],   // k_base
        (const float*)d_in[7],   // b
        (float*)d_out);
}

// round 3
// speedup vs baseline: 2.0046x; 2.0046x over previous
#include <cuda_runtime.h>
#include <cuda_fp16.h>
#include <cstdint>

// ----------------------------------------------------------------------------
// Dims
// ----------------------------------------------------------------------------
#define S_TOK 8192
#define D_IN  4096
#define NGRP  4
#define HDIM  128
#define NQ    4096
#define NK    1024
#define NF    5120

// GEMM tiling (legacy mma.sync fp16 m16n8k16, base sm_100 compatible)
#define BM 128
#define BN 256
#define BK 32
#define STAGES 4
#define KT (D_IN / BK)              // 128
#define PITCH_H 40                  // halfs per row (80B) -> conflict-free ldmatrix
#define A_STG_H (BM * PITCH_H)      // 5120 halfs
#define B_STG_H (BN * PITCH_H)      // 10240 halfs
#define SMEM_BYTES (STAGES * (A_STG_H + B_STG_H) * 2)   // 122880

// Device scratch
__device__ __half g_Ah[(size_t)S_TOK * D_IN];           // hidden in fp16
__device__ __half g_Wh[(size_t)NF * D_IN];              // [q_w ; k_w] in fp16
__device__ float  g_C[(size_t)S_TOK * NF];              // projection outputs

// ----------------------------------------------------------------------------
// helpers
// ----------------------------------------------------------------------------
__device__ __forceinline__ uint32_t smem_u32(const void* p) {
    uint32_t a;
    asm("{ .reg .u64 t; cvta.to.shared.u64 t, %1; cvt.u32.u64 %0, t; }"
        : "=r"(a) : "l"(p));
    return a;
}
__device__ __forceinline__ void cp_async16(uint32_t dst, const void* src) {
    asm volatile("cp.async.cg.shared.global [%0], [%1], 16;"
                 :: "r"(dst), "l"(src) : "memory");
}
__device__ __forceinline__ void cp_commit() {
    asm volatile("cp.async.commit_group;" ::: "memory");
}
template <int N>
__device__ __forceinline__ void cp_wait() {
    asm volatile("cp.async.wait_group %0;" :: "n"(N) : "memory");
}
__device__ __forceinline__ void ldsm_x4(uint32_t* r, uint32_t addr) {
    asm volatile("ldmatrix.sync.aligned.m8n8.x4.shared.b16 {%0,%1,%2,%3}, [%4];"
                 : "=r"(r[0]), "=r"(r[1]), "=r"(r[2]), "=r"(r[3]) : "r"(addr));
}
__device__ __forceinline__ void mma_f16(float* c, const uint32_t* a,
                                        const uint32_t* b) {
    asm volatile(
        "mma.sync.aligned.m16n8k16.row.col.f32.f16.f16.f32 "
        "{%0,%1,%2,%3}, {%4,%5,%6,%7}, {%8,%9}, {%0,%1,%2,%3};"
        : "+f"(c[0]), "+f"(c[1]), "+f"(c[2]), "+f"(c[3])
        : "r"(a[0]), "r"(a[1]), "r"(a[2]), "r"(a[3]), "r"(b[0]), "r"(b[1]));
}

// ----------------------------------------------------------------------------
// fp32 -> fp16 convert (vectorized, 4 floats / thread)
// ----------------------------------------------------------------------------
__global__ void __launch_bounds__(256)
cvt_kernel(const float* __restrict__ src, __half* __restrict__ dst, int n4) {
    int i = blockIdx.x * blockDim.x + threadIdx.x;
    if (i < n4) {
        float4 v = reinterpret_cast<const float4*>(src)[i];
        reinterpret_cast<__half2*>(dst)[2 * i]     = __floats2half2_rn(v.x, v.y);
        reinterpret_cast<__half2*>(dst)[2 * i + 1] = __floats2half2_rn(v.z, v.w);
    }
}

// ----------------------------------------------------------------------------
// Kernel 1: fused projection GEMM  C[8192, 5120] = hs * Wt   (fp16 inputs)
// grid: (NF/BN = 20, S_TOK/BM = 64), 512 threads, warp grid 4x4 (32x64 / warp)
// ----------------------------------------------------------------------------
__global__ void __launch_bounds__(512, 1)
gemm_kernel()
{
    extern __shared__ __half sm[];
    __half* As = sm;                              // [STAGES][BM][PITCH_H]
    __half* Bs = sm + STAGES * A_STG_H;           // [STAGES][BN][PITCH_H]

    const int tid   = threadIdx.x;
    const int ntile = blockIdx.x;   // 0..19
    const int mtile = blockIdx.y;   // 0..63

    const __half* Asrc = g_Ah + (size_t)mtile * BM * D_IN;
    const __half* Bsrc = g_Wh + (size_t)ntile * BN * D_IN;

    const uint32_t as_base = smem_u32(As);
    const uint32_t bs_base = smem_u32(Bs);

    // loader: 16B granules. A: 512 granules (1/thread), B: 1024 (2/thread)
    const int gr = tid >> 2;        // 0..127
    const int gg = tid & 3;         // granule col 0..3 (8 halfs each)

    auto load_stage = [&](int kt, int s) {
        const uint32_t a_st = as_base + (uint32_t)(s * A_STG_H) * 2;
        const uint32_t b_st = bs_base + (uint32_t)(s * B_STG_H) * 2;
        const int kc = kt * BK + gg * 8;
        cp_async16(a_st + (gr * PITCH_H + gg * 8) * 2,
                   Asrc + (size_t)gr * D_IN + kc);
        #pragma unroll
        for (int i = 0; i < 2; i++) {
            const int row = gr + i * 128;
            cp_async16(b_st + (row * PITCH_H + gg * 8) * 2,
                       Bsrc + (size_t)row * D_IN + kc);
        }
        cp_commit();
    };

    load_stage(0, 0);
    load_stage(1, 1);
    load_stage(2, 2);

    const int wid = tid >> 5;
    const int ln  = tid & 31;
    const int wm  = wid & 3;        // 32-row strip
    const int wn  = wid >> 2;       // 64-col strip

    float acc[2][8][4];
    #pragma unroll
    for (int mi = 0; mi < 2; mi++)
        #pragma unroll
        for (int ni = 0; ni < 8; ni++)
            #pragma unroll
            for (int j = 0; j < 4; j++) acc[mi][ni][j] = 0.0f;

    // ldmatrix lane addressing (byte offsets within a stage)
    // A (x4 -> a0..a3 of one 16x16): row = r0 + (ln&15), col = ks*16 + (ln>>4)*8
    const uint32_t a_off =
        (uint32_t)(((wm * 32 + (ln & 15)) * PITCH_H + (ln >> 4) * 8) * 2);
    // B (x4 -> b0,b1 of two adjacent ni): n = n0 + (ln&7) + ((ln>>4)<<3),
    //                                     col = ks*16 + ((ln>>3)&1)*8
    const uint32_t b_off =
        (uint32_t)(((wn * 64 + (ln & 7) + ((ln >> 4) << 3)) * PITCH_H +
                    ((ln >> 3) & 1) * 8) * 2);

    for (int kt = 0; kt < KT; kt++) {
        const int s = kt & (STAGES - 1);
        cp_wait<2>();
        __syncthreads();
        if (kt + 3 < KT) load_stage(kt + 3, (kt + 3) & (STAGES - 1));

        const uint32_t a_s = as_base + (uint32_t)(s * A_STG_H) * 2 + a_off;
        const uint32_t b_s = bs_base + (uint32_t)(s * B_STG_H) * 2 + b_off;

        #pragma unroll
        for (int ks = 0; ks < 2; ks++) {
            uint32_t af[2][4], bf[8][2];
            #pragma unroll
            for (int mi = 0; mi < 2; mi++)
                ldsm_x4(af[mi], a_s + (mi * 16 * PITCH_H + ks * 16) * 2);
            #pragma unroll
            for (int pr = 0; pr < 4; pr++) {
                uint32_t t[4];
                ldsm_x4(t, b_s + (pr * 16 * PITCH_H + ks * 16) * 2);
                bf[2 * pr][0]     = t[0];
                bf[2 * pr][1]     = t[1];
                bf[2 * pr + 1][0] = t[2];
                bf[2 * pr + 1][1] = t[3];
            }
            #pragma unroll
            for (int mi = 0; mi < 2; mi++)
                #pragma unroll
                for (int ni = 0; ni < 8; ni++)
                    mma_f16(acc[mi][ni], af[mi], bf[ni]);
        }
    }

    // epilogue: 128x256 tile -> g_C (W unified, so fbase is just ntile*BN)
    const int lr = ln >> 2, lc = ln & 3;
    const size_t fbase = (size_t)ntile * BN;
    #pragma unroll
    for (int mi = 0; mi < 2; mi++) {
        const int row = mtile * BM + wm * 32 + mi * 16 + lr;
        float* dst = g_C + (size_t)row * NF + fbase + wn * 64 + 2 * lc;
        #pragma unroll
        for (int ni = 0; ni < 8; ni++) {
            *reinterpret_cast<float2*>(dst + ni * 8) =
                make_float2(acc[mi][ni][0], acc[mi][ni][1]);
            *reinterpret_cast<float2*>(dst + ni * 8 + 8 * NF) =
                make_float2(acc[mi][ni][2], acc[mi][ni][3]);
        }
    }
}

// ----------------------------------------------------------------------------
// Kernel 2: per-token score epilogue (warp h of block s handles head h)
// ----------------------------------------------------------------------------
__global__ void __launch_bounds__(256)
score_kernel(const float* __restrict__ q_b, const float* __restrict__ q_nw,
             const float* __restrict__ k_nw, const float* __restrict__ k_base,
             const float* __restrict__ bias, float* __restrict__ out)
{
    const int s = blockIdx.x;
    const int h = threadIdx.x >> 5;
    const int lane = threadIdx.x & 31;
    const float* Crow = g_C + (size_t)s * NF;

    float4 kv = *reinterpret_cast<const float4*>(Crow + NQ + h * HDIM + lane * 4);
    float ss = kv.x * kv.x + kv.y * kv.y + kv.z * kv.z + kv.w * kv.w;
    #pragma unroll
    for (int o = 16; o > 0; o >>= 1) ss += __shfl_xor_sync(0xffffffffu, ss, o);
    const float rk = rsqrtf(ss * (1.0f / HDIM) + 1e-6f);
    float4 knw = *reinterpret_cast<const float4*>(k_nw + lane * 4);
    const float kn0 = kv.x * rk * knw.x, kn1 = kv.y * rk * knw.y;
    const float kn2 = kv.z * rk * knw.z, kn3 = kv.w * rk * knw.w;

    float4 kb  = *reinterpret_cast<const float4*>(k_base + h * HDIM + lane * 4);
    float4 qnw = *reinterpret_cast<const float4*>(q_nw + lane * 4);

    const float inv_scale = 0.08838834764831845f;   // 1/sqrt(128)
    float acc = 0.0f;

    #pragma unroll
    for (int g = 0; g < NGRP; g++) {
        const int f0 = h * (NGRP * HDIM) + g * HDIM + lane * 4;
        float4 qv  = *reinterpret_cast<const float4*>(Crow + f0);
        float4 qbv = *reinterpret_cast<const float4*>(q_b + f0);
        const float q0 = qv.x + qbv.x, q1 = qv.y + qbv.y;
        const float q2 = qv.z + qbv.z, q3 = qv.w + qbv.w;

        float qs = q0 * q0 + q1 * q1 + q2 * q2 + q3 * q3;
        #pragma unroll
        for (int o = 16; o > 0; o >>= 1) qs += __shfl_xor_sync(0xffffffffu, qs, o);
        const float rq = rsqrtf(qs * (1.0f / HDIM) + 1e-6f);

        const float qn0 = q0 * rq * qnw.x, qn1 = q1 * rq * qnw.y;
        const float qn2 = q2 * rq * qnw.z, qn3 = q3 * rq * qnw.w;

        float dm = kn0 * qn0 + kn1 * qn1 + kn2 * qn2 + kn3 * qn3;
        float db = kb.x * qn0 + kb.y * qn1 + kb.z * qn2 + kb.w * qn3;
        #pragma unroll
        for (int o = 16; o > 0; o >>= 1) {
            dm += __shfl_xor_sync(0xffffffffu, dm, o);
            db += __shfl_xor_sync(0xffffffffu, db, o);
        }

        const float logit = dm * inv_scale + bias[h * NGRP + g];
        acc += 1.0f / (1.0f + expf(db * inv_scale - logit));
    }

    if (lane == 0) out[(size_t)h * S_TOK + s] = acc * 0.25f;
}

// ----------------------------------------------------------------------------
// Host launch
// ----------------------------------------------------------------------------
extern "C" void kernel_launch(void* const* d_in, const int* in_sizes, int n_in,
                              void* d_out, int out_size) {
    (void)in_sizes; (void)n_in; (void)out_size;

    static __half* p_Ah = nullptr;
    static __half* p_Wh = nullptr;
    if (!p_Ah) {
        void* p;
        cudaGetSymbolAddress(&p, g_Ah); p_Ah = (__half*)p;
        cudaGetSymbolAddress(&p, g_Wh); p_Wh = (__half*)p;
        cudaFuncSetAttribute(gemm_kernel,
                             cudaFuncAttributeMaxDynamicSharedMemorySize,
                             SMEM_BYTES);
    }

    const int nA = (S_TOK * D_IN) / 4;   // 8388608
    const int nQ = (NQ * D_IN) / 4;      // 4194304
    const int nK = (NK * D_IN) / 4;      // 1048576

    cvt_kernel<<<(nA + 255) / 256, 256>>>((const float*)d_in[0], p_Ah, nA);
    cvt_kernel<<<(nQ + 255) / 256, 256>>>((const float*)d_in[1], p_Wh, nQ);
    cvt_kernel<<<(nK + 255) / 256, 256>>>((const float*)d_in[3],
                                          p_Wh + (size_t)NQ * D_IN, nK);

    gemm_kernel<<<dim3(NF / BN, S_TOK / BM), 512, SMEM_BYTES>>>();

    score_kernel<<<S_TOK, 256>>>(
        (const float*)d_in[2],   // q_b
        (const float*)d_in[4],   // q_norm_w
        (const float*)d_in[5],   // k_norm_w
        (const float*)d_in[6],   // k_base
        (const float*)d_in[7],   // b
        (float*)d_out);
}

// round 4
// speedup vs baseline: 2.0148x; 1.0051x over previous
#include <cuda_runtime.h>
#include <cuda_fp16.h>
#include <cstdint>

// ----------------------------------------------------------------------------
// Dims
// ----------------------------------------------------------------------------
#define S_TOK 8192
#define D_IN  4096
#define NGRP  4
#define HDIM  128
#define NQ    4096
#define NK    1024
#define NF    5120

// GEMM tiling (legacy mma.sync fp16 m16n8k16, base sm_100 compatible)
#define BM 128
#define BN 256
#define BK 32
#define STAGES 4
#define KT (D_IN / BK)              // 128
#define PITCH_H 40                  // halfs per row (80B) -> conflict-free ldmatrix
#define A_STG_H (BM * PITCH_H)      // 5120 halfs
#define B_STG_H (BN * PITCH_H)      // 10240 halfs
#define SMEM_BYTES (STAGES * (A_STG_H + B_STG_H) * 2)   // 122880

// Device scratch
__device__ __half g_Ah[(size_t)S_TOK * D_IN];           // hidden in fp16
__device__ __half g_Wh[(size_t)NF * D_IN];              // [q_w ; k_w] in fp16
__device__ __half g_Ch[(size_t)S_TOK * NF];             // projection outputs fp16

// ----------------------------------------------------------------------------
// helpers
// ----------------------------------------------------------------------------
__device__ __forceinline__ uint32_t smem_u32(const void* p) {
    uint32_t a;
    asm("{ .reg .u64 t; cvta.to.shared.u64 t, %1; cvt.u32.u64 %0, t; }"
        : "=r"(a) : "l"(p));
    return a;
}
__device__ __forceinline__ void cp_async16(uint32_t dst, const void* src) {
    asm volatile("cp.async.cg.shared.global [%0], [%1], 16;"
                 :: "r"(dst), "l"(src) : "memory");
}
__device__ __forceinline__ void cp_commit() {
    asm volatile("cp.async.commit_group;" ::: "memory");
}
template <int N>
__device__ __forceinline__ void cp_wait() {
    asm volatile("cp.async.wait_group %0;" :: "n"(N) : "memory");
}
__device__ __forceinline__ void ldsm_x4(uint32_t* r, uint32_t addr) {
    asm volatile("ldmatrix.sync.aligned.m8n8.x4.shared.b16 {%0,%1,%2,%3}, [%4];"
                 : "=r"(r[0]), "=r"(r[1]), "=r"(r[2]), "=r"(r[3]) : "r"(addr));
}
__device__ __forceinline__ void mma_f16(float* c, const uint32_t* a,
                                        const uint32_t* b) {
    asm volatile(
        "mma.sync.aligned.m16n8k16.row.col.f32.f16.f16.f32 "
        "{%0,%1,%2,%3}, {%4,%5,%6,%7}, {%8,%9}, {%0,%1,%2,%3};"
        : "+f"(c[0]), "+f"(c[1]), "+f"(c[2]), "+f"(c[3])
        : "r"(a[0]), "r"(a[1]), "r"(a[2]), "r"(b[0]), "r"(b[1]), "r"(a[3]));
}

// NOTE: operand order must match PTX register list; keep canonical form:
__device__ __forceinline__ void mma_f16_c(float* c, const uint32_t* a,
                                          const uint32_t* b) {
    asm volatile(
        "mma.sync.aligned.m16n8k16.row.col.f32.f16.f16.f32 "
        "{%0,%1,%2,%3}, {%4,%5,%6,%7}, {%8,%9}, {%0,%1,%2,%3};"
        : "+f"(c[0]), "+f"(c[1]), "+f"(c[2]), "+f"(c[3])
        : "r"(a[0]), "r"(a[1]), "r"(a[2]), "r"(a[3]), "r"(b[0]), "r"(b[1]));
}

// ----------------------------------------------------------------------------
// fused fp32 -> fp16 convert for A, Wq, Wk (one launch, 16B granules)
// ----------------------------------------------------------------------------
#define N4_A ((S_TOK * D_IN) / 4)       // 8388608
#define N4_Q ((NQ * D_IN) / 4)          // 4194304
#define N4_K ((NK * D_IN) / 4)          // 1048576
#define N4_TOT (N4_A + N4_Q + N4_K)

__global__ void __launch_bounds__(256)
cvt_all_kernel(const float* __restrict__ A, const float* __restrict__ Wq,
               const float* __restrict__ Wk) {
    int i = blockIdx.x * blockDim.x + threadIdx.x;
    if (i >= N4_TOT) return;
    const float* src;
    __half* dst;
    int j;
    if (i < N4_A)            { j = i;                src = A;  dst = g_Ah; }
    else if (i < N4_A + N4_Q){ j = i - N4_A;         src = Wq; dst = g_Wh; }
    else                     { j = i - N4_A - N4_Q;  src = Wk;
                               dst = g_Wh + (size_t)NQ * D_IN; }
    float4 v = reinterpret_cast<const float4*>(src)[j];
    reinterpret_cast<__half2*>(dst)[2 * j]     = __floats2half2_rn(v.x, v.y);
    reinterpret_cast<__half2*>(dst)[2 * j + 1] = __floats2half2_rn(v.z, v.w);
}

// ----------------------------------------------------------------------------
// Kernel 1: fused projection GEMM  C[8192, 5120] = hs * Wt   (fp16 in, fp16 out)
// grid: (NF/BN = 20, S_TOK/BM = 64), 512 threads, warp grid 4x4 (32x64 / warp)
// ----------------------------------------------------------------------------
__global__ void __launch_bounds__(512, 1)
gemm_kernel()
{
    extern __shared__ __half sm[];
    __half* As = sm;                              // [STAGES][BM][PITCH_H]
    __half* Bs = sm + STAGES * A_STG_H;           // [STAGES][BN][PITCH_H]

    const int tid   = threadIdx.x;
    const int ntile = blockIdx.x;   // 0..19
    const int mtile = blockIdx.y;   // 0..63

    const __half* Asrc = g_Ah + (size_t)mtile * BM * D_IN;
    const __half* Bsrc = g_Wh + (size_t)ntile * BN * D_IN;

    const uint32_t as_base = smem_u32(As);
    const uint32_t bs_base = smem_u32(Bs);

    const int gr = tid >> 2;        // 0..127
    const int gg = tid & 3;         // granule col (8 halfs each)

    auto load_stage = [&](int kt, int s) {
        const uint32_t a_st = as_base + (uint32_t)(s * A_STG_H) * 2;
        const uint32_t b_st = bs_base + (uint32_t)(s * B_STG_H) * 2;
        const int kc = kt * BK + gg * 8;
        cp_async16(a_st + (gr * PITCH_H + gg * 8) * 2,
                   Asrc + (size_t)gr * D_IN + kc);
        #pragma unroll
        for (int i = 0; i < 2; i++) {
            const int row = gr + i * 128;
            cp_async16(b_st + (row * PITCH_H + gg * 8) * 2,
                       Bsrc + (size_t)row * D_IN + kc);
        }
        cp_commit();
    };

    load_stage(0, 0);
    load_stage(1, 1);
    load_stage(2, 2);

    const int wid = tid >> 5;
    const int ln  = tid & 31;
    const int wm  = wid & 3;        // 32-row strip
    const int wn  = wid >> 2;       // 64-col strip

    float acc[2][8][4];
    #pragma unroll
    for (int mi = 0; mi < 2; mi++)
        #pragma unroll
        for (int ni = 0; ni < 8; ni++)
            #pragma unroll
            for (int j = 0; j < 4; j++) acc[mi][ni][j] = 0.0f;

    const uint32_t a_off =
        (uint32_t)(((wm * 32 + (ln & 15)) * PITCH_H + (ln >> 4) * 8) * 2);
    const uint32_t b_off =
        (uint32_t)(((wn * 64 + (ln & 7) + ((ln >> 4) << 3)) * PITCH_H +
                    ((ln >> 3) & 1) * 8) * 2);

    for (int kt = 0; kt < KT; kt++) {
        const int s = kt & (STAGES - 1);
        cp_wait<2>();
        __syncthreads();
        if (kt + 3 < KT) load_stage(kt + 3, (kt + 3) & (STAGES - 1));

        const uint32_t a_s = as_base + (uint32_t)(s * A_STG_H) * 2 + a_off;
        const uint32_t b_s = bs_base + (uint32_t)(s * B_STG_H) * 2 + b_off;

        #pragma unroll
        for (int ks = 0; ks < 2; ks++) {
            uint32_t af[2][4], bf[8][2];
            #pragma unroll
            for (int mi = 0; mi < 2; mi++)
                ldsm_x4(af[mi], a_s + (mi * 16 * PITCH_H + ks * 16) * 2);
            #pragma unroll
            for (int pr = 0; pr < 4; pr++) {
                uint32_t t[4];
                ldsm_x4(t, b_s + (pr * 16 * PITCH_H + ks * 16) * 2);
                bf[2 * pr][0]     = t[0];
                bf[2 * pr][1]     = t[1];
                bf[2 * pr + 1][0] = t[2];
                bf[2 * pr + 1][1] = t[3];
            }
            #pragma unroll
            for (int mi = 0; mi < 2; mi++)
                #pragma unroll
                for (int ni = 0; ni < 8; ni++)
                    mma_f16_c(acc[mi][ni], af[mi], bf[ni]);
        }
    }

    // epilogue: 128x256 tile -> g_Ch (fp16)
    const int lr = ln >> 2, lc = ln & 3;
    const size_t fbase = (size_t)ntile * BN;
    #pragma unroll
    for (int mi = 0; mi < 2; mi++) {
        const int row = mtile * BM + wm * 32 + mi * 16 + lr;
        __half* dst = g_Ch + (size_t)row * NF + fbase + wn * 64 + 2 * lc;
        #pragma unroll
        for (int ni = 0; ni < 8; ni++) {
            *reinterpret_cast<__half2*>(dst + ni * 8) =
                __floats2half2_rn(acc[mi][ni][0], acc[mi][ni][1]);
            *reinterpret_cast<__half2*>(dst + ni * 8 + 8 * NF) =
                __floats2half2_rn(acc[mi][ni][2], acc[mi][ni][3]);
        }
    }
}

// ----------------------------------------------------------------------------
// Kernel 2: per-token score epilogue (warp h of block s handles head h)
// ----------------------------------------------------------------------------
__device__ __forceinline__ float4 ld_half4(const __half* p) {
    const __half2* p2 = reinterpret_cast<const __half2*>(p);
    float2 a = __half22float2(p2[0]);
    float2 b = __half22float2(p2[1]);
    return make_float4(a.x, a.y, b.x, b.y);
}

__global__ void __launch_bounds__(256)
score_kernel(const float* __restrict__ q_b, const float* __restrict__ q_nw,
             const float* __restrict__ k_nw, const float* __restrict__ k_base,
             const float* __restrict__ bias, float* __restrict__ out)
{
    const int s = blockIdx.x;
    const int h = threadIdx.x >> 5;
    const int lane = threadIdx.x & 31;
    const __half* Crow = g_Ch + (size_t)s * NF;

    float4 kv = ld_half4(Crow + NQ + h * HDIM + lane * 4);
    float ss = kv.x * kv.x + kv.y * kv.y + kv.z * kv.z + kv.w * kv.w;
    #pragma unroll
    for (int o = 16; o > 0; o >>= 1) ss += __shfl_xor_sync(0xffffffffu, ss, o);
    const float rk = rsqrtf(ss * (1.0f / HDIM) + 1e-6f);
    float4 knw = *reinterpret_cast<const float4*>(k_nw + lane * 4);
    const float kn0 = kv.x * rk * knw.x, kn1 = kv.y * rk * knw.y;
    const float kn2 = kv.z * rk * knw.z, kn3 = kv.w * rk * knw.w;

    float4 kb  = *reinterpret_cast<const float4*>(k_base + h * HDIM + lane * 4);
    float4 qnw = *reinterpret_cast<const float4*>(q_nw + lane * 4);

    const float inv_scale = 0.08838834764831845f;   // 1/sqrt(128)
    float acc = 0.0f;

    #pragma unroll
    for (int g = 0; g < NGRP; g++) {
        const int f0 = h * (NGRP * HDIM) + g * HDIM + lane * 4;
        float4 qv  = ld_half4(Crow + f0);
        float4 qbv = *reinterpret_cast<const float4*>(q_b + f0);
        const float q0 = qv.x + qbv.x, q1 = qv.y + qbv.y;
        const float q2 = qv.z + qbv.z, q3 = qv.w + qbv.w;

        float qs = q0 * q0 + q1 * q1 + q2 * q2 + q3 * q3;
        #pragma unroll
        for (int o = 16; o > 0; o >>= 1) qs += __shfl_xor_sync(0xffffffffu, qs, o);
        const float rq = rsqrtf(qs * (1.0f / HDIM) + 1e-6f);

        const float qn0 = q0 * rq * qnw.x, qn1 = q1 * rq * qnw.y;
        const float qn2 = q2 * rq * qnw.z, qn3 = q3 * rq * qnw.w;

        float dm = kn0 * qn0 + kn1 * qn1 + kn2 * qn2 + kn3 * qn3;
        float db = kb.x * qn0 + kb.y * qn1 + kb.z * qn2 + kb.w * qn3;
        #pragma unroll
        for (int o = 16; o > 0; o >>= 1) {
            dm += __shfl_xor_sync(0xffffffffu, dm, o);
            db += __shfl_xor_sync(0xffffffffu, db, o);
        }

        const float logit = dm * inv_scale + bias[h * NGRP + g];
        acc += 1.0f / (1.0f + expf(db * inv_scale - logit));
    }

    if (lane == 0) out[(size_t)h * S_TOK + s] = acc * 0.25f;
}

// ----------------------------------------------------------------------------
// Host launch
// ----------------------------------------------------------------------------
extern "C" void kernel_launch(void* const* d_in, const int* in_sizes, int n_in,
                              void* d_out, int out_size) {
    (void)in_sizes; (void)n_in; (void)out_size;

    static bool init_done = false;
    if (!init_done) {
        cudaFuncSetAttribute(gemm_kernel,
                             cudaFuncAttributeMaxDynamicSharedMemorySize,
                             SMEM_BYTES);
        init_done = true;
    }

    cvt_all_kernel<<<(N4_TOT + 255) / 256, 256>>>(
        (const float*)d_in[0],   // hidden_states
        (const float*)d_in[1],   // q_w
        (const float*)d_in[3]);  // k_w

    gemm_kernel<<<dim3(NF / BN, S_TOK / BM), 512, SMEM_BYTES>>>();

    score_kernel<<<S_TOK, 256>>>(
        (const float*)d_in[2],   // q_b
        (const float*)d_in[4],   // q_norm_w
        (const float*)d_in[5],   // k_norm_w
        (const float*)d_in[6],   // k_base
        (const float*)d_in[7],   // b
        (float*)d_out);
}

// round 5
// speedup vs baseline: 2.0166x; 1.0009x over previous
#include <cuda_runtime.h>
#include <cuda_fp16.h>
#include <cstdint>

// ----------------------------------------------------------------------------
// Dims
// ----------------------------------------------------------------------------
#define S_TOK 8192
#define D_IN  4096
#define NGRP  4
#define HDIM  128
#define NQ    4096
#define NK    1024
#define NF    5120

// GEMM tiling (legacy mma.sync fp16 m16n8k16, base sm_100 compatible)
#define BM 128
#define BN 256
#define BK 32
#define STAGES 4
#define KT (D_IN / BK)              // 128
#define PITCH_H 40                  // halfs per row (80B) -> conflict-free ldmatrix
#define A_STG_H (BM * PITCH_H)      // 5120 halfs
#define B_STG_H (BN * PITCH_H)      // 10240 halfs
#define SMEM_BYTES (STAGES * (A_STG_H + B_STG_H) * 2)   // 122880

// Device scratch
__device__ __half g_Ah[(size_t)S_TOK * D_IN];           // hidden in fp16
__device__ __half g_Wh[(size_t)NF * D_IN];              // [q_w ; k_w] in fp16
__device__ __half g_Ch[(size_t)S_TOK * NF];             // projection outputs fp16

// ----------------------------------------------------------------------------
// helpers
// ----------------------------------------------------------------------------
__device__ __forceinline__ uint32_t smem_u32(const void* p) {
    uint32_t a;
    asm("{ .reg .u64 t; cvta.to.shared.u64 t, %1; cvt.u32.u64 %0, t; }"
        : "=r"(a) : "l"(p));
    return a;
}
__device__ __forceinline__ void cp_async16(uint32_t dst, const void* src) {
    asm volatile("cp.async.cg.shared.global [%0], [%1], 16;"
                 :: "r"(dst), "l"(src) : "memory");
}
__device__ __forceinline__ void cp_commit() {
    asm volatile("cp.async.commit_group;" ::: "memory");
}
template <int N>
__device__ __forceinline__ void cp_wait() {
    asm volatile("cp.async.wait_group %0;" :: "n"(N) : "memory");
}
__device__ __forceinline__ void ldsm_x4(uint32_t* r, uint32_t addr) {
    asm volatile("ldmatrix.sync.aligned.m8n8.x4.shared.b16 {%0,%1,%2,%3}, [%4];"
                 : "=r"(r[0]), "=r"(r[1]), "=r"(r[2]), "=r"(r[3]) : "r"(addr));
}
__device__ __forceinline__ void mma_f16(float* c, const uint32_t* a,
                                        const uint32_t* b) {
    asm volatile(
        "mma.sync.aligned.m16n8k16.row.col.f32.f16.f16.f32 "
        "{%0,%1,%2,%3}, {%4,%5,%6,%7}, {%8,%9}, {%0,%1,%2,%3};"
        : "+f"(c[0]), "+f"(c[1]), "+f"(c[2]), "+f"(c[3])
        : "r"(a[0]), "r"(a[1]), "r"(a[2]), "r"(b[0]), "r"(b[1]), "r"(a[3]));
}

// NOTE: operand order must match PTX register list; keep canonical form:
__device__ __forceinline__ void mma_f16_c(float* c, const uint32_t* a,
                                          const uint32_t* b) {
    asm volatile(
        "mma.sync.aligned.m16n8k16.row.col.f32.f16.f16.f32 "
        "{%0,%1,%2,%3}, {%4,%5,%6,%7}, {%8,%9}, {%0,%1,%2,%3};"
        : "+f"(c[0]), "+f"(c[1]), "+f"(c[2]), "+f"(c[3])
        : "r"(a[0]), "r"(a[1]), "r"(a[2]), "r"(a[3]), "r"(b[0]), "r"(b[1]));
}

// ----------------------------------------------------------------------------
// fused fp32 -> fp16 convert for A, Wq, Wk (one launch, 16B granules)
// ----------------------------------------------------------------------------
#define N4_A ((S_TOK * D_IN) / 4)       // 8388608
#define N4_Q ((NQ * D_IN) / 4)          // 4194304
#define N4_K ((NK * D_IN) / 4)          // 1048576
#define N4_TOT (N4_A + N4_Q + N4_K)

__global__ void __launch_bounds__(256)
cvt_all_kernel(const float* __restrict__ A, const float* __restrict__ Wq,
               const float* __restrict__ Wk) {
    int i = blockIdx.x * blockDim.x + threadIdx.x;
    if (i >= N4_TOT) return;
    const float* src;
    __half* dst;
    int j;
    if (i < N4_A)            { j = i;                src = A;  dst = g_Ah; }
    else if (i < N4_A + N4_Q){ j = i - N4_A;         src = Wq; dst = g_Wh; }
    else                     { j = i - N4_A - N4_Q;  src = Wk;
                               dst = g_Wh + (size_t)NQ * D_IN; }
    float4 v = reinterpret_cast<const float4*>(src)[j];
    reinterpret_cast<__half2*>(dst)[2 * j]     = __floats2half2_rn(v.x, v.y);
    reinterpret_cast<__half2*>(dst)[2 * j + 1] = __floats2half2_rn(v.z, v.w);
}

// ----------------------------------------------------------------------------
// Kernel 1: fused projection GEMM  C[8192, 5120] = hs * Wt   (fp16 in, fp16 out)
// grid: (NF/BN = 20, S_TOK/BM = 64), 512 threads, warp grid 4x4 (32x64 / warp)
// ----------------------------------------------------------------------------
__global__ void __launch_bounds__(512, 1)
gemm_kernel()
{
    extern __shared__ __half sm[];
    __half* As = sm;                              // [STAGES][BM][PITCH_H]
    __half* Bs = sm + STAGES * A_STG_H;           // [STAGES][BN][PITCH_H]

    const int tid   = threadIdx.x;
    const int ntile = blockIdx.x;   // 0..19
    const int mtile = blockIdx.y;   // 0..63

    const __half* Asrc = g_Ah + (size_t)mtile * BM * D_IN;
    const __half* Bsrc = g_Wh + (size_t)ntile * BN * D_IN;

    const uint32_t as_base = smem_u32(As);
    const uint32_t bs_base = smem_u32(Bs);

    const int gr = tid >> 2;        // 0..127
    const int gg = tid & 3;         // granule col (8 halfs each)

    auto load_stage = [&](int kt, int s) {
        const uint32_t a_st = as_base + (uint32_t)(s * A_STG_H) * 2;
        const uint32_t b_st = bs_base + (uint32_t)(s * B_STG_H) * 2;
        const int kc = kt * BK + gg * 8;
        cp_async16(a_st + (gr * PITCH_H + gg * 8) * 2,
                   Asrc + (size_t)gr * D_IN + kc);
        #pragma unroll
        for (int i = 0; i < 2; i++) {
            const int row = gr + i * 128;
            cp_async16(b_st + (row * PITCH_H + gg * 8) * 2,
                       Bsrc + (size_t)row * D_IN + kc);
        }
        cp_commit();
    };

    load_stage(0, 0);
    load_stage(1, 1);
    load_stage(2, 2);

    const int wid = tid >> 5;
    const int ln  = tid & 31;
    const int wm  = wid & 3;        // 32-row strip
    const int wn  = wid >> 2;       // 64-col strip

    float acc[2][8][4];
    #pragma unroll
    for (int mi = 0; mi < 2; mi++)
        #pragma unroll
        for (int ni = 0; ni < 8; ni++)
            #pragma unroll
            for (int j = 0; j < 4; j++) acc[mi][ni][j] = 0.0f;

    const uint32_t a_off =
        (uint32_t)(((wm * 32 + (ln & 15)) * PITCH_H + (ln >> 4) * 8) * 2);
    const uint32_t b_off =
        (uint32_t)(((wn * 64 + (ln & 7) + ((ln >> 4) << 3)) * PITCH_H +
                    ((ln >> 3) & 1) * 8) * 2);

    for (int kt = 0; kt < KT; kt++) {
        const int s = kt & (STAGES - 1);
        cp_wait<2>();
        __syncthreads();
        if (kt + 3 < KT) load_stage(kt + 3, (kt + 3) & (STAGES - 1));

        const uint32_t a_s = as_base + (uint32_t)(s * A_STG_H) * 2 + a_off;
        const uint32_t b_s = bs_base + (uint32_t)(s * B_STG_H) * 2 + b_off;

        #pragma unroll
        for (int ks = 0; ks < 2; ks++) {
            uint32_t af[2][4], bf[8][2];
            #pragma unroll
            for (int mi = 0; mi < 2; mi++)
                ldsm_x4(af[mi], a_s + (mi * 16 * PITCH_H + ks * 16) * 2);
            #pragma unroll
            for (int pr = 0; pr < 4; pr++) {
                uint32_t t[4];
                ldsm_x4(t, b_s + (pr * 16 * PITCH_H + ks * 16) * 2);
                bf[2 * pr][0]     = t[0];
                bf[2 * pr][1]     = t[1];
                bf[2 * pr + 1][0] = t[2];
                bf[2 * pr + 1][1] = t[3];
            }
            #pragma unroll
            for (int mi = 0; mi < 2; mi++)
                #pragma unroll
                for (int ni = 0; ni < 8; ni++)
                    mma_f16_c(acc[mi][ni], af[mi], bf[ni]);
        }
    }

    // epilogue: 128x256 tile -> g_Ch (fp16)
    const int lr = ln >> 2, lc = ln & 3;
    const size_t fbase = (size_t)ntile * BN;
    #pragma unroll
    for (int mi = 0; mi < 2; mi++) {
        const int row = mtile * BM + wm * 32 + mi * 16 + lr;
        __half* dst = g_Ch + (size_t)row * NF + fbase + wn * 64 + 2 * lc;
        #pragma unroll
        for (int ni = 0; ni < 8; ni++) {
            *reinterpret_cast<__half2*>(dst + ni * 8) =
                __floats2half2_rn(acc[mi][ni][0], acc[mi][ni][1]);
            *reinterpret_cast<__half2*>(dst + ni * 8 + 8 * NF) =
                __floats2half2_rn(acc[mi][ni][2], acc[mi][ni][3]);
        }
    }
}

// ----------------------------------------------------------------------------
// Kernel 2: per-token score epilogue (warp h of block s handles head h)
// ----------------------------------------------------------------------------
__device__ __forceinline__ float4 ld_half4(const __half* p) {
    const __half2* p2 = reinterpret_cast<const __half2*>(p);
    float2 a = __half22float2(p2[0]);
    float2 b = __half22float2(p2[1]);
    return make_float4(a.x, a.y, b.x, b.y);
}

__global__ void __launch_bounds__(256)
score_kernel(const float* __restrict__ q_b, const float* __restrict__ q_nw,
             const float* __restrict__ k_nw, const float* __restrict__ k_base,
             const float* __restrict__ bias, float* __restrict__ out)
{
    const int s = blockIdx.x;
    const int h = threadIdx.x >> 5;
    const int lane = threadIdx.x & 31;
    const __half* Crow = g_Ch + (size_t)s * NF;

    float4 kv = ld_half4(Crow + NQ + h * HDIM + lane * 4);
    float ss = kv.x * kv.x + kv.y * kv.y + kv.z * kv.z + kv.w * kv.w;
    #pragma unroll
    for (int o = 16; o > 0; o >>= 1) ss += __shfl_xor_sync(0xffffffffu, ss, o);
    const float rk = rsqrtf(ss * (1.0f / HDIM) + 1e-6f);
    float4 knw = *reinterpret_cast<const float4*>(k_nw + lane * 4);
    const float kn0 = kv.x * rk * knw.x, kn1 = kv.y * rk * knw.y;
    const float kn2 = kv.z * rk * knw.z, kn3 = kv.w * rk * knw.w;

    float4 kb  = *reinterpret_cast<const float4*>(k_base + h * HDIM + lane * 4);
    float4 qnw = *reinterpret_cast<const float4*>(q_nw + lane * 4);

    const float inv_scale = 0.08838834764831845f;   // 1/sqrt(128)
    float acc = 0.0f;

    #pragma unroll
    for (int g = 0; g < NGRP; g++) {
        const int f0 = h * (NGRP * HDIM) + g * HDIM + lane * 4;
        float4 qv  = ld_half4(Crow + f0);
        float4 qbv = *reinterpret_cast<const float4*>(q_b + f0);
        const float q0 = qv.x + qbv.x, q1 = qv.y + qbv.y;
        const float q2 = qv.z + qbv.z, q3 = qv.w + qbv.w;

        float qs = q0 * q0 + q1 * q1 + q2 * q2 + q3 * q3;
        #pragma unroll
        for (int o = 16; o > 0; o >>= 1) qs += __shfl_xor_sync(0xffffffffu, qs, o);
        const float rq = rsqrtf(qs * (1.0f / HDIM) + 1e-6f);

        const float qn0 = q0 * rq * qnw.x, qn1 = q1 * rq * qnw.y;
        const float qn2 = q2 * rq * qnw.z, qn3 = q3 * rq * qnw.w;

        float dm = kn0 * qn0 + kn1 * qn1 + kn2 * qn2 + kn3 * qn3;
        float db = kb.x * qn0 + kb.y * qn1 + kb.z * qn2 + kb.w * qn3;
        #pragma unroll
        for (int o = 16; o > 0; o >>= 1) {
            dm += __shfl_xor_sync(0xffffffffu, dm, o);
            db += __shfl_xor_sync(0xffffffffu, db, o);
        }

        const float logit = dm * inv_scale + bias[h * NGRP + g];
        acc += 1.0f / (1.0f + expf(db * inv_scale - logit));
    }

    if (lane == 0) out[(size_t)h * S_TOK + s] = acc * 0.25f;
}

// ----------------------------------------------------------------------------
// Host launch
// ----------------------------------------------------------------------------
extern "C" void kernel_launch(void* const* d_in, const int* in_sizes, int n_in,
                              void* d_out, int out_size) {
    (void)in_sizes; (void)n_in; (void)out_size;

    static bool init_done = false;
    if (!init_done) {
        cudaFuncSetAttribute(gemm_kernel,
                             cudaFuncAttributeMaxDynamicSharedMemorySize,
                             SMEM_BYTES);
        init_done = true;
    }

    cvt_all_kernel<<<(N4_TOT + 255) / 256, 256>>>(
        (const float*)d_in[0],   // hidden_states
        (const float*)d_in[1],   // q_w
        (const float*)d_in[3]);  // k_w

    gemm_kernel<<<dim3(NF / BN, S_TOK / BM), 512, SMEM_BYTES>>>();

    score_kernel<<<S_TOK, 256>>>(
        (const float*)d_in[2],   // q_b
        (const float*)d_in[4],   // q_norm_w
        (const float*)d_in[5],   // k_norm_w
        (const float*)d_in[6],   // k_base
        (const float*)d_in[7],   // b
        (float*)d_out);
}